// round 2
// baseline (speedup 1.0000x reference)
#include <cuda_runtime.h>
#include <math.h>
#include <float.h>

#define B_   2
#define S_   2048
#define D_   1024
#define H_   16
#define DK_  64
#define MTOK (B_*S_)   // 4096

// Scratch (allocation-free rule: __device__ globals)
__device__ float g_q[MTOK * D_];
__device__ float g_k[MTOK * D_];
__device__ float g_v[MTOK * D_];
__device__ float g_ctx[MTOK * D_];
__device__ float g_p[B_ * H_ * S_ * S_];   // 512 MB scores/probs

// ---------------------------------------------------------------------------
// C[M,N] = A[M,K] @ W[N,K]^T + bias[N]
// 64x64 block tile, 256 threads, 4x4 per-thread micro-tile, k-tiles of 16.
// ---------------------------------------------------------------------------
__global__ __launch_bounds__(256) void gemm_bias_kernel(
    const float* __restrict__ A, const float* __restrict__ W,
    const float* __restrict__ bias, float* __restrict__ C,
    int M, int N, int K)
{
    __shared__ float As[64][17];
    __shared__ float Bs[16][65];
    const int tid = threadIdx.x;
    const int tx = tid & 15, ty = tid >> 4;
    const int m0 = blockIdx.y << 6, n0 = blockIdx.x << 6;

    float acc[4][4] = {};
    for (int kt = 0; kt < K; kt += 16) {
#pragma unroll
        for (int l = 0; l < 4; ++l) {
            int idx = tid + l * 256;
            int i = idx >> 4, kk = idx & 15;
            As[i][kk] = A[(size_t)(m0 + i) * K + kt + kk];
            Bs[kk][i] = W[(size_t)(n0 + i) * K + kt + kk];
        }
        __syncthreads();
#pragma unroll
        for (int kk = 0; kk < 16; ++kk) {
            float a[4], b[4];
#pragma unroll
            for (int r = 0; r < 4; ++r) a[r] = As[ty * 4 + r][kk];
#pragma unroll
            for (int c = 0; c < 4; ++c) b[c] = Bs[kk][tx * 4 + c];
#pragma unroll
            for (int r = 0; r < 4; ++r)
#pragma unroll
                for (int c = 0; c < 4; ++c)
                    acc[r][c] = fmaf(a[r], b[c], acc[r][c]);
        }
        __syncthreads();
    }
#pragma unroll
    for (int r = 0; r < 4; ++r) {
        int m = m0 + ty * 4 + r;
#pragma unroll
        for (int c = 0; c < 4; ++c) {
            int n = n0 + tx * 4 + c;
            C[(size_t)m * N + n] = acc[r][c] + bias[n];
        }
    }
}

// ---------------------------------------------------------------------------
// scores[bh][q][k] = (Q_h[q,:] . K_h[k,:]) * 1/8, masked to -10000 where mask==0
// grid: (S/64 key-tiles, S/64 query-tiles, B*H)
// ---------------------------------------------------------------------------
__global__ __launch_bounds__(256) void scores_kernel(const int* __restrict__ mask)
{
    const int k0 = blockIdx.x << 6, q0 = blockIdx.y << 6, bh = blockIdx.z;
    const int b = bh >> 4, h = bh & 15;
    const float* Qh = g_q + (size_t)b * S_ * D_ + h * DK_;
    const float* Kh = g_k + (size_t)b * S_ * D_ + h * DK_;
    float* P = g_p + (size_t)bh * S_ * S_;

    __shared__ float As[64][17];
    __shared__ float Bs[16][65];
    const int tid = threadIdx.x;
    const int tx = tid & 15, ty = tid >> 4;

    float acc[4][4] = {};
    for (int kd = 0; kd < DK_; kd += 16) {
#pragma unroll
        for (int l = 0; l < 4; ++l) {
            int idx = tid + l * 256;
            int i = idx >> 4, kk = idx & 15;
            As[i][kk] = Qh[(size_t)(q0 + i) * D_ + kd + kk];
            Bs[kk][i] = Kh[(size_t)(k0 + i) * D_ + kd + kk];
        }
        __syncthreads();
#pragma unroll
        for (int kk = 0; kk < 16; ++kk) {
            float a[4], bb[4];
#pragma unroll
            for (int r = 0; r < 4; ++r) a[r] = As[ty * 4 + r][kk];
#pragma unroll
            for (int c = 0; c < 4; ++c) bb[c] = Bs[kk][tx * 4 + c];
#pragma unroll
            for (int r = 0; r < 4; ++r)
#pragma unroll
                for (int c = 0; c < 4; ++c)
                    acc[r][c] = fmaf(a[r], bb[c], acc[r][c]);
        }
        __syncthreads();
    }
#pragma unroll
    for (int r = 0; r < 4; ++r) {
        int q = q0 + ty * 4 + r;
#pragma unroll
        for (int c = 0; c < 4; ++c) {
            int k = k0 + tx * 4 + c;
            float s = acc[r][c] * 0.125f;       // 1/sqrt(64)
            if (mask[b * S_ + k] == 0) s = -10000.0f;
            P[(size_t)q * S_ + k] = s;
        }
    }
}

// ---------------------------------------------------------------------------
// Row softmax over the key dim (S=2048). One block per (bh, q) row.
// ---------------------------------------------------------------------------
__global__ __launch_bounds__(256) void softmax_kernel()
{
    float* row = g_p + (size_t)blockIdx.x * S_;
    const int tid = threadIdx.x;
    __shared__ float red[256];

    float v[8];
    float m = -FLT_MAX;
#pragma unroll
    for (int j = 0; j < 8; ++j) {
        v[j] = row[tid + j * 256];
        m = fmaxf(m, v[j]);
    }
    red[tid] = m; __syncthreads();
    for (int s = 128; s > 0; s >>= 1) {
        if (tid < s) red[tid] = fmaxf(red[tid], red[tid + s]);
        __syncthreads();
    }
    m = red[0]; __syncthreads();

    float sum = 0.0f;
#pragma unroll
    for (int j = 0; j < 8; ++j) {
        v[j] = __expf(v[j] - m);
        sum += v[j];
    }
    red[tid] = sum; __syncthreads();
    for (int s = 128; s > 0; s >>= 1) {
        if (tid < s) red[tid] += red[tid + s];
        __syncthreads();
    }
    float inv = 1.0f / red[0];
#pragma unroll
    for (int j = 0; j < 8; ++j) row[tid + j * 256] = v[j] * inv;
}

// ---------------------------------------------------------------------------
// ctx[b,q,h*64+d] = sum_k P[bh][q][k] * V_h[k][d]
// grid: (S/64 query-tiles, B*H)
// ---------------------------------------------------------------------------
__global__ __launch_bounds__(256) void attnv_kernel()
{
    const int q0 = blockIdx.x << 6, bh = blockIdx.y;
    const int b = bh >> 4, h = bh & 15;
    const float* P  = g_p + (size_t)bh * S_ * S_;
    const float* Vh = g_v   + (size_t)b * S_ * D_ + h * DK_;
    float*       O  = g_ctx + (size_t)b * S_ * D_ + h * DK_;

    __shared__ float As[64][17];
    __shared__ float Bs[16][65];
    const int tid = threadIdx.x;
    const int tx = tid & 15, ty = tid >> 4;

    float acc[4][4] = {};
    for (int kt = 0; kt < S_; kt += 16) {
#pragma unroll
        for (int l = 0; l < 4; ++l) {
            int idx = tid + l * 256;
            int i = idx >> 4, kk = idx & 15;
            As[i][kk] = P[(size_t)(q0 + i) * S_ + kt + kk];
            int kv = idx >> 6, j = idx & 63;
            Bs[kv][j] = Vh[(size_t)(kt + kv) * D_ + j];
        }
        __syncthreads();
#pragma unroll
        for (int kk = 0; kk < 16; ++kk) {
            float a[4], bb[4];
#pragma unroll
            for (int r = 0; r < 4; ++r) a[r] = As[ty * 4 + r][kk];
#pragma unroll
            for (int c = 0; c < 4; ++c) bb[c] = Bs[kk][tx * 4 + c];
#pragma unroll
            for (int r = 0; r < 4; ++r)
#pragma unroll
                for (int c = 0; c < 4; ++c)
                    acc[r][c] = fmaf(a[r], bb[c], acc[r][c]);
        }
        __syncthreads();
    }
#pragma unroll
    for (int r = 0; r < 4; ++r) {
        int q = q0 + ty * 4 + r;
#pragma unroll
        for (int c = 0; c < 4; ++c)
            O[(size_t)q * D_ + tx * 4 + c] = acc[r][c];
    }
}

// ---------------------------------------------------------------------------
extern "C" void kernel_launch(void* const* d_in, const int* in_sizes, int n_in,
                              void* d_out, int out_size)
{
    const float* query = (const float*)d_in[0];
    const float* key   = (const float*)d_in[1];
    const float* value = (const float*)d_in[2];
    const int*   mask  = (const int*)d_in[3];
    const float* Wq = (const float*)d_in[4];  const float* bq = (const float*)d_in[5];
    const float* Wk = (const float*)d_in[6];  const float* bk = (const float*)d_in[7];
    const float* Wv = (const float*)d_in[8];  const float* bv = (const float*)d_in[9];
    const float* Wo = (const float*)d_in[10]; const float* bo = (const float*)d_in[11];
    float* out = (float*)d_out;

    float *gq, *gk, *gv, *gctx;
    cudaGetSymbolAddress((void**)&gq,   g_q);
    cudaGetSymbolAddress((void**)&gk,   g_k);
    cudaGetSymbolAddress((void**)&gv,   g_v);
    cudaGetSymbolAddress((void**)&gctx, g_ctx);

    dim3 gproj(D_ / 64, MTOK / 64);   // (16, 64)
    gemm_bias_kernel<<<gproj, 256>>>(query, Wq, bq, gq, MTOK, D_, D_);
    gemm_bias_kernel<<<gproj, 256>>>(key,   Wk, bk, gk, MTOK, D_, D_);
    gemm_bias_kernel<<<gproj, 256>>>(value, Wv, bv, gv, MTOK, D_, D_);

    scores_kernel<<<dim3(S_ / 64, S_ / 64, B_ * H_), 256>>>(mask);
    softmax_kernel<<<B_ * H_ * S_, 256>>>();
    attnv_kernel<<<dim3(S_ / 64, B_ * H_), 256>>>();

    gemm_bias_kernel<<<gproj, 256>>>(gctx, Wo, bo, out, MTOK, D_, D_);
}